// round 16
// baseline (speedup 1.0000x reference)
#include <cuda_runtime.h>
#include <math.h>

// SBEceLoss: logits [N,100] f32, labels [N] i64 -> scalar ece (f32)
// Contiguous per-block spans (HBM row-buffer locality, R14 win) combined with
// a 4-deep TMA ring buffer (3 tiles in flight per block):
//   - 32-row tiles (12.8KB); ONE cp.async.bulk + mbarrier per tile
//   - buffer k&3, parity (k>>2)&1
//   - inner scan: LDS + FSETP + FSEL + SEL per element
//   - certification via merge intermediates: min(pairmax01, pairmax23) > -4
//     && -16 < m < 8  ->  acc == 0 proven exactly (fallback otherwise)
//   - block 0 precomputes the 100x15 bin-softmax coef table at START
//   - per-block shared histogram -> global REDs; last block -> ECE + reset.

#define C_CLASSES 100
#define NB 15
#define TILE_ROWS 32
#define TILE_FLOATS (TILE_ROWS * C_CLASSES)   // 3200
#define TILE_BYTES  (TILE_FLOATS * 4)         // 12800
#define NBUF 4
#define THREADS 128
#define FULLM 0xffffffffu

__device__ int   g_cnt[C_CLASSES];
__device__ int   g_acc[C_CLASSES];
__device__ float g_coef[C_CLASSES][NB];
__device__ unsigned g_done;

__device__ __forceinline__ void mbar_init(unsigned mbar, unsigned count) {
    asm volatile("mbarrier.init.shared.b64 [%0], %1;" :: "r"(mbar), "r"(count) : "memory");
}
__device__ __forceinline__ void mbar_expect_tx(unsigned mbar, unsigned bytes) {
    asm volatile("mbarrier.arrive.expect_tx.shared.b64 _, [%0], %1;"
                 :: "r"(mbar), "r"(bytes) : "memory");
}
__device__ __forceinline__ void bulk_g2s(unsigned sdst, const void* gsrc,
                                         unsigned bytes, unsigned mbar) {
    asm volatile("cp.async.bulk.shared::cta.global.mbarrier::complete_tx::bytes "
                 "[%0], [%1], %2, [%3];"
                 :: "r"(sdst), "l"(gsrc), "r"(bytes), "r"(mbar) : "memory");
}
__device__ __forceinline__ void mbar_wait(unsigned mbar, unsigned parity) {
    asm volatile(
        "{\n\t"
        ".reg .pred P;\n\t"
        "WAIT_%=:\n\t"
        "mbarrier.try_wait.parity.acquire.cta.shared::cta.b64 P, [%0], %1, 0x989680;\n\t"
        "@P bra.uni DONE_%=;\n\t"
        "bra.uni WAIT_%=;\n\t"
        "DONE_%=:\n\t"
        "}"
        :: "r"(mbar), "r"(parity) : "memory");
}

__global__ void __launch_bounds__(THREADS)
fused_kernel(const float* __restrict__ logits,
             const long long* __restrict__ labels,
             int n_rows, float* __restrict__ out) {
    extern __shared__ __align__(16) float sdyn[];            // NBUF * 3200 floats
    __shared__ __align__(8) unsigned long long mbar_st[NBUF];
    __shared__ int  s_cnt[C_CLASSES];
    __shared__ int  s_acc[C_CLASSES];
    __shared__ bool s_last;

    const int tid = threadIdx.x;
    for (int i = tid; i < C_CLASSES; i += THREADS) { s_cnt[i] = 0; s_acc[i] = 0; }

    unsigned mb[NBUF], sb[NBUF];
    #pragma unroll
    for (int i = 0; i < NBUF; i++) {
        mb[i] = (unsigned)__cvta_generic_to_shared(&mbar_st[i]);
        sb[i] = (unsigned)__cvta_generic_to_shared(&sdyn[i * TILE_FLOATS]);
    }
    if (tid == 0) {
        #pragma unroll
        for (int i = 0; i < NBUF; i++) mbar_init(mb[i], 1);
    }
    __syncthreads();   // mbarriers visible before any TMA targets them

    const int tiles = (n_rows + TILE_ROWS - 1) / TILE_ROWS;
    const int tpb   = (tiles + gridDim.x - 1) / gridDim.x;   // tiles per block
    const int t0    = blockIdx.x * tpb;                      // contiguous span
    const int t1    = min(t0 + tpb, tiles);
    const int nloc  = t1 - t0;                               // may be <= 0

    // ---- prologue: issue local tiles k = 0..NBUF-2 (contiguous) ----
    if (tid == 0) {
        #pragma unroll
        for (int k = 0; k < NBUF - 1; k++) {
            if (k < nloc) {
                int t = t0 + k;
                unsigned bytes = (unsigned)(min(TILE_ROWS, n_rows - t * TILE_ROWS) * 400);
                mbar_expect_tx(mb[k], bytes);
                bulk_g2s(sb[k], (const char*)logits + (size_t)t * TILE_BYTES, bytes, mb[k]);
            }
        }
    }

    // ---- block 0: precompute bin-softmax coef table (overlaps streaming) ----
    // Ordered before finalize readers by the __threadfence preceding g_done.
    if (blockIdx.x == 0 && tid < C_CLASSES) {
        float cf = (float)tid;
        float d[NB];
        float dmax = __int_as_float(0xff800000);
        #pragma unroll
        for (int jj = 0; jj < NB; jj++) {
            float aj = (float)((2 * jj + 1) / 30.0);
            float tt = cf - aj;
            d[jj] = -(tt * tt) / 0.01f;
            dmax = fmaxf(dmax, d[jj]);
        }
        float denom = 0.0f;
        #pragma unroll
        for (int jj = 0; jj < NB; jj++) denom += expf(d[jj] - dmax);
        #pragma unroll
        for (int jj = 0; jj < NB; jj++) g_coef[tid][jj] = expf(d[jj] - dmax) / denom;
    }

    const int q = tid & 3;               // quarter within the row
    for (int k = 0; k < nloc; k++) {
        const int tile = t0 + k;
        // issue tile k+NBUF-1 into buffer (k+NBUF-1)&3 (consumed at iteration
        // k-1; that iteration's __syncthreads ordered all reads before refill)
        int nk = k + NBUF - 1;
        if (nk < nloc && tid == 0) {
            int nb = nk & (NBUF - 1);
            int nt = t0 + nk;
            unsigned bytes = (unsigned)(min(TILE_ROWS, n_rows - nt * TILE_ROWS) * 400);
            mbar_expect_tx(mb[nb], bytes);
            bulk_g2s(sb[nb], (const char*)logits + (size_t)nt * TILE_BYTES, bytes, mb[nb]);
        }

        // wait for current tile: buffer k&3, phase parity (k>>2)&1
        const int b = k & (NBUF - 1);
        mbar_wait(mb[b], (k >> 2) & 1);

        // ---- thread-local quarter-row scan (conflict-free: stride 25) ----
        const float* rp = &sdyn[b * TILE_FLOATS + tid * 25];
        float m   = rp[0];
        int   idx = q * 25;
        #pragma unroll
        for (int i = 1; i < 25; i++) {
            float x = rp[i];
            bool p = x > m;                  // strict > keeps first occurrence
            m   = p ? x : m;
            idx = p ? q * 25 + i : idx;
        }

        // ---- merge 4 quarters: (value desc, index asc) + cert lower bound ----
        {
            float om = __shfl_xor_sync(FULLM, m,   1);
            int   oi = __shfl_xor_sync(FULLM, idx, 1);
            bool take = (om > m) || (om == m && oi < idx);
            m   = take ? om : m;
            idx = take ? oi : idx;
        }
        float second_lb;
        {
            float om = __shfl_xor_sync(FULLM, m,   2);
            int   oi = __shfl_xor_sync(FULLM, idx, 2);
            second_lb = fminf(m, om);   // a REAL element distinct from the argmax
            bool take = (om > m) || (om == m && oi < idx);
            m   = take ? om : m;
            idx = take ? oi : idx;
        }

        int row = tile * TILE_ROWS + (tid >> 2);
        if (q == 0 && row < n_rows) {
            // cert: 2nd element > -4 > m-12 (since m < 8) and |m| < 16 =>
            // log(sumexp) >= log(1+e^-12) = 6.1e-6 > ulp(16)/2 => max logprob
            // strictly < 0 => never equals an integer label => acc = 0.
            bool good = (second_lb > -4.0f) && (m < 8.0f) && (m > -16.0f);
            if (!good) {   // statistically never taken
                const float* rb = &sdyn[b * TILE_FLOATS + (tid >> 2) * C_CLASSES];
                float sv = 0.0f;
                for (int i = 0; i < C_CLASSES; i++) sv += expf(rb[i] - m);
                float pred = m - (m + logf(sv));
                if (pred == (float)labels[row]) atomicAdd(&s_acc[idx], 1);
            }
            atomicAdd(&s_cnt[idx], 1);
        }
        __syncthreads();   // all reads of buf b done before it is re-filled
    }

    // ---- flush block histogram to global ----
    for (int i = tid; i < C_CLASSES; i += THREADS) {
        int c = s_cnt[i]; if (c) atomicAdd(&g_cnt[i], c);
        int a = s_acc[i]; if (a) atomicAdd(&g_acc[i], a);
    }
    __threadfence();     // orders histogram REDs AND block 0's g_coef stores
    __syncthreads();

    if (tid == 0) {
        unsigned rank = atomicAdd(&g_done, 1u);
        s_last = (rank == gridDim.x - 1);
    }
    __syncthreads();
    if (!s_last) return;

    // ================= finalize (last block only; alias dynamic SMEM) ======
    float (*s_coef)[NB + 1] = reinterpret_cast<float(*)[NB + 1]>(&sdyn[0]);  // 1600 f
    int*   s_c2   = reinterpret_cast<int*>(&sdyn[1600]);
    int*   s_a2   = reinterpret_cast<int*>(&sdyn[1728]);
    float* s_sum  = &sdyn[1856];
    float* s_conf = &sdyn[1872];
    float* s_accs = &sdyn[1888];

    int t = tid;
    if (t < C_CLASSES) {
        s_c2[t] = __ldcg(&g_cnt[t]);
        s_a2[t] = __ldcg(&g_acc[t]);
        #pragma unroll
        for (int jj = 0; jj < NB; jj++) s_coef[t][jj] = __ldcg(&g_coef[t][jj]);
        g_cnt[t] = 0;     // reset for next graph replay
        g_acc[t] = 0;
    }
    if (t == 0) g_done = 0;
    __syncthreads();

    if (t < NB) {
        float sum_c = 0.0f, sum_cc = 0.0f, sum_a = 0.0f;
        for (int c = 0; c < C_CLASSES; c++) {
            int cnt = s_c2[c];
            int ac  = s_a2[c];
            if ((cnt | ac) == 0) continue;
            float coeff = s_coef[c][t];
            float fcnt  = (float)cnt;   // exact: cnt < 2^24
            float cf    = (float)c;
            sum_c  += fcnt * coeff;
            sum_cc += fcnt * cf * coeff;
            sum_a  += (float)ac * coeff;
        }
        s_sum[t]  = sum_c;
        s_conf[t] = sum_cc;
        s_accs[t] = sum_a;
    }
    __syncthreads();

    if (t == 0) {
        float tot = 0.0f;
        #pragma unroll
        for (int jj = 0; jj < NB; jj++) tot += fabsf(s_sum[jj]);
        float wden = fmaxf(tot, 1e-5f);
        float acc2 = 0.0f;
        #pragma unroll
        for (int jj = 0; jj < NB; jj++) {
            float den = fmaxf(s_sum[jj], 1e-5f);
            float bc  = s_conf[jj] / den;
            float ba  = s_accs[jj] / den;
            float w   = s_sum[jj] / wden;
            float df  = bc - ba;
            acc2 += df * df * w;
        }
        out[0] = sqrtf(acc2);
    }
}

extern "C" void kernel_launch(void* const* d_in, const int* in_sizes, int n_in,
                              void* d_out, int out_size) {
    const float*     logits = (const float*)d_in[0];
    const long long* labels = (const long long*)d_in[1];
    float*           out    = (float*)d_out;
    int n_rows = in_sizes[1];  // labels count = N

    const int smem_bytes = NBUF * TILE_BYTES;  // 51200
    cudaFuncSetAttribute(fused_kernel,
                         cudaFuncAttributeMaxDynamicSharedMemorySize, smem_bytes);
    // 592 = 4 blocks/SM * 148 SMs, single wave; ~28 contiguous tiles per block,
    // 3 TMA copies in flight per block
    fused_kernel<<<592, THREADS, smem_bytes>>>(logits, labels, n_rows, out);
}

// round 17
// speedup vs baseline: 1.0447x; 1.0447x over previous
#include <cuda_runtime.h>
#include <math.h>

// SBEceLoss: logits [N,100] f32, labels [N] i64 -> scalar ece (f32)
// Champion geometry (R14: 1024 contiguous streams, 2-deep, 8 blocks/SM) with
// the copy engine swapped to BULK TMA (one strictly-sequential 12.8KB burst
// per tile instead of 896 interleaved LDGSTS -> preserves row-buffer locality
// and removes LSU issue cost):
//   - 32-row tiles (12.8KB) double-buffered; cp.async.bulk + mbarrier per tile
//   - buffer k&1, parity (k>>1)&1
//   - inner scan: LDS + FSETP + FSEL + SEL per element
//   - certification via merge intermediates: min(pairmax01, pairmax23) > -4
//     && -16 < m < 8  ->  acc == 0 proven exactly (fallback otherwise)
//   - block 0 precomputes the 100x15 bin-softmax coef table at START
//   - per-block shared histogram -> global REDs; last block -> ECE + reset.

#define C_CLASSES 100
#define NB 15
#define TILE_ROWS 32
#define TILE_FLOATS (TILE_ROWS * C_CLASSES)   // 3200
#define TILE_BYTES  (TILE_FLOATS * 4)         // 12800
#define NBUF 2
#define THREADS 128
#define FULLM 0xffffffffu

__device__ int   g_cnt[C_CLASSES];
__device__ int   g_acc[C_CLASSES];
__device__ float g_coef[C_CLASSES][NB];
__device__ unsigned g_done;

__device__ __forceinline__ void mbar_init(unsigned mbar, unsigned count) {
    asm volatile("mbarrier.init.shared.b64 [%0], %1;" :: "r"(mbar), "r"(count) : "memory");
}
__device__ __forceinline__ void mbar_expect_tx(unsigned mbar, unsigned bytes) {
    asm volatile("mbarrier.arrive.expect_tx.shared.b64 _, [%0], %1;"
                 :: "r"(mbar), "r"(bytes) : "memory");
}
__device__ __forceinline__ void bulk_g2s(unsigned sdst, const void* gsrc,
                                         unsigned bytes, unsigned mbar) {
    asm volatile("cp.async.bulk.shared::cta.global.mbarrier::complete_tx::bytes "
                 "[%0], [%1], %2, [%3];"
                 :: "r"(sdst), "l"(gsrc), "r"(bytes), "r"(mbar) : "memory");
}
__device__ __forceinline__ void mbar_wait(unsigned mbar, unsigned parity) {
    asm volatile(
        "{\n\t"
        ".reg .pred P;\n\t"
        "WAIT_%=:\n\t"
        "mbarrier.try_wait.parity.acquire.cta.shared::cta.b64 P, [%0], %1, 0x989680;\n\t"
        "@P bra.uni DONE_%=;\n\t"
        "bra.uni WAIT_%=;\n\t"
        "DONE_%=:\n\t"
        "}"
        :: "r"(mbar), "r"(parity) : "memory");
}

__global__ void __launch_bounds__(THREADS)
fused_kernel(const float* __restrict__ logits,
             const long long* __restrict__ labels,
             int n_rows, float* __restrict__ out) {
    extern __shared__ __align__(16) float sdyn[];            // NBUF * 3200 floats
    __shared__ __align__(8) unsigned long long mbar_st[NBUF];
    __shared__ int  s_cnt[C_CLASSES];
    __shared__ int  s_acc[C_CLASSES];
    __shared__ bool s_last;

    const int tid = threadIdx.x;
    for (int i = tid; i < C_CLASSES; i += THREADS) { s_cnt[i] = 0; s_acc[i] = 0; }

    unsigned mb[NBUF], sb[NBUF];
    #pragma unroll
    for (int i = 0; i < NBUF; i++) {
        mb[i] = (unsigned)__cvta_generic_to_shared(&mbar_st[i]);
        sb[i] = (unsigned)__cvta_generic_to_shared(&sdyn[i * TILE_FLOATS]);
    }
    if (tid == 0) {
        #pragma unroll
        for (int i = 0; i < NBUF; i++) mbar_init(mb[i], 1);
    }
    __syncthreads();   // mbarriers visible before any TMA targets them

    const int tiles = (n_rows + TILE_ROWS - 1) / TILE_ROWS;
    const int tpb   = (tiles + gridDim.x - 1) / gridDim.x;   // tiles per block
    const int t0    = blockIdx.x * tpb;                      // contiguous span
    const int t1    = min(t0 + tpb, tiles);
    const int nloc  = t1 - t0;                               // may be <= 0

    // ---- prologue: first owned tile into buffer 0 (one bulk burst) ----
    if (tid == 0 && nloc > 0) {
        unsigned bytes = (unsigned)(min(TILE_ROWS, n_rows - t0 * TILE_ROWS) * 400);
        mbar_expect_tx(mb[0], bytes);
        bulk_g2s(sb[0], (const char*)logits + (size_t)t0 * TILE_BYTES, bytes, mb[0]);
    }

    // ---- block 0: precompute bin-softmax coef table (overlaps streaming) ----
    // Ordered before finalize readers by the __threadfence preceding g_done.
    if (blockIdx.x == 0 && tid < C_CLASSES) {
        float cf = (float)tid;
        float d[NB];
        float dmax = __int_as_float(0xff800000);
        #pragma unroll
        for (int jj = 0; jj < NB; jj++) {
            float aj = (float)((2 * jj + 1) / 30.0);
            float tt = cf - aj;
            d[jj] = -(tt * tt) / 0.01f;
            dmax = fmaxf(dmax, d[jj]);
        }
        float denom = 0.0f;
        #pragma unroll
        for (int jj = 0; jj < NB; jj++) denom += expf(d[jj] - dmax);
        #pragma unroll
        for (int jj = 0; jj < NB; jj++) g_coef[tid][jj] = expf(d[jj] - dmax) / denom;
    }

    const int q = tid & 3;               // quarter within the row
    for (int k = 0; k < nloc; k++) {
        const int tile = t0 + k;
        // issue tile k+1 into the other buffer (consumed at iteration k-1;
        // that iteration's __syncthreads ordered all reads before refill)
        if (k + 1 < nloc && tid == 0) {
            int nb = (k + 1) & 1;
            int nt = tile + 1;
            unsigned bytes = (unsigned)(min(TILE_ROWS, n_rows - nt * TILE_ROWS) * 400);
            mbar_expect_tx(mb[nb], bytes);
            bulk_g2s(sb[nb], (const char*)logits + (size_t)nt * TILE_BYTES, bytes, mb[nb]);
        }

        // wait for current tile: buffer k&1, phase parity (k>>1)&1
        const int b = k & 1;
        mbar_wait(mb[b], (k >> 1) & 1);

        // ---- thread-local quarter-row scan (conflict-free: stride 25) ----
        const float* rp = &sdyn[b * TILE_FLOATS + tid * 25];
        float m   = rp[0];
        int   idx = q * 25;
        #pragma unroll
        for (int i = 1; i < 25; i++) {
            float x = rp[i];
            bool p = x > m;                  // strict > keeps first occurrence
            m   = p ? x : m;
            idx = p ? q * 25 + i : idx;
        }

        // ---- merge 4 quarters: (value desc, index asc) + cert lower bound ----
        {
            float om = __shfl_xor_sync(FULLM, m,   1);
            int   oi = __shfl_xor_sync(FULLM, idx, 1);
            bool take = (om > m) || (om == m && oi < idx);
            m   = take ? om : m;
            idx = take ? oi : idx;
        }
        float second_lb;
        {
            float om = __shfl_xor_sync(FULLM, m,   2);
            int   oi = __shfl_xor_sync(FULLM, idx, 2);
            second_lb = fminf(m, om);   // a REAL element distinct from the argmax
            bool take = (om > m) || (om == m && oi < idx);
            m   = take ? om : m;
            idx = take ? oi : idx;
        }

        int row = tile * TILE_ROWS + (tid >> 2);
        if (q == 0 && row < n_rows) {
            // cert: 2nd element > -4 > m-12 (since m < 8) and |m| < 16 =>
            // log(sumexp) >= log(1+e^-12) = 6.1e-6 > ulp(16)/2 => max logprob
            // strictly < 0 => never equals an integer label => acc = 0.
            bool good = (second_lb > -4.0f) && (m < 8.0f) && (m > -16.0f);
            if (!good) {   // statistically never taken
                const float* rb = &sdyn[b * TILE_FLOATS + (tid >> 2) * C_CLASSES];
                float sv = 0.0f;
                for (int i = 0; i < C_CLASSES; i++) sv += expf(rb[i] - m);
                float pred = m - (m + logf(sv));
                if (pred == (float)labels[row]) atomicAdd(&s_acc[idx], 1);
            }
            atomicAdd(&s_cnt[idx], 1);
        }
        __syncthreads();   // all reads of buf b done before it is re-filled
    }

    // ---- flush block histogram to global ----
    for (int i = tid; i < C_CLASSES; i += THREADS) {
        int c = s_cnt[i]; if (c) atomicAdd(&g_cnt[i], c);
        int a = s_acc[i]; if (a) atomicAdd(&g_acc[i], a);
    }
    __threadfence();     // orders histogram REDs AND block 0's g_coef stores
    __syncthreads();

    if (tid == 0) {
        unsigned rank = atomicAdd(&g_done, 1u);
        s_last = (rank == gridDim.x - 1);
    }
    __syncthreads();
    if (!s_last) return;

    // ================= finalize (last block only; alias dynamic SMEM) ======
    float (*s_coef)[NB + 1] = reinterpret_cast<float(*)[NB + 1]>(&sdyn[0]);  // 1600 f
    int*   s_c2   = reinterpret_cast<int*>(&sdyn[1600]);
    int*   s_a2   = reinterpret_cast<int*>(&sdyn[1728]);
    float* s_sum  = &sdyn[1856];
    float* s_conf = &sdyn[1872];
    float* s_accs = &sdyn[1888];

    int t = tid;
    if (t < C_CLASSES) {
        s_c2[t] = __ldcg(&g_cnt[t]);
        s_a2[t] = __ldcg(&g_acc[t]);
        #pragma unroll
        for (int jj = 0; jj < NB; jj++) s_coef[t][jj] = __ldcg(&g_coef[t][jj]);
        g_cnt[t] = 0;     // reset for next graph replay
        g_acc[t] = 0;
    }
    if (t == 0) g_done = 0;
    __syncthreads();

    if (t < NB) {
        float sum_c = 0.0f, sum_cc = 0.0f, sum_a = 0.0f;
        for (int c = 0; c < C_CLASSES; c++) {
            int cnt = s_c2[c];
            int ac  = s_a2[c];
            if ((cnt | ac) == 0) continue;
            float coeff = s_coef[c][t];
            float fcnt  = (float)cnt;   // exact: cnt < 2^24
            float cf    = (float)c;
            sum_c  += fcnt * coeff;
            sum_cc += fcnt * cf * coeff;
            sum_a  += (float)ac * coeff;
        }
        s_sum[t]  = sum_c;
        s_conf[t] = sum_cc;
        s_accs[t] = sum_a;
    }
    __syncthreads();

    if (t == 0) {
        float tot = 0.0f;
        #pragma unroll
        for (int jj = 0; jj < NB; jj++) tot += fabsf(s_sum[jj]);
        float wden = fmaxf(tot, 1e-5f);
        float acc2 = 0.0f;
        #pragma unroll
        for (int jj = 0; jj < NB; jj++) {
            float den = fmaxf(s_sum[jj], 1e-5f);
            float bc  = s_conf[jj] / den;
            float ba  = s_accs[jj] / den;
            float w   = s_sum[jj] / wden;
            float df  = bc - ba;
            acc2 += df * df * w;
        }
        out[0] = sqrtf(acc2);
    }
}

extern "C" void kernel_launch(void* const* d_in, const int* in_sizes, int n_in,
                              void* d_out, int out_size) {
    const float*     logits = (const float*)d_in[0];
    const long long* labels = (const long long*)d_in[1];
    float*           out    = (float*)d_out;
    int n_rows = in_sizes[1];  // labels count = N

    const int smem_bytes = NBUF * TILE_BYTES;  // 25600
    cudaFuncSetAttribute(fused_kernel,
                         cudaFuncAttributeMaxDynamicSharedMemorySize, smem_bytes);
    // 1024 blocks x 16 contiguous tiles (204.8 KB span), 8 blocks/SM resident
    fused_kernel<<<1024, THREADS, smem_bytes>>>(logits, labels, n_rows, out);
}